// round 7
// baseline (speedup 1.0000x reference)
#include <cuda_runtime.h>

#define BATCH  32
#define HW     3136
#define C      256
#define C4     64            // C/4
#define CR     64
#define PPC    32            // pixels per chunk
#define CHUNKS 98            // HW / PPC

// Scratch (allocation-free per harness rules)
__device__ float g_partial[BATCH * CHUNKS * C];
__device__ float g_gate[BATCH * C];
__device__ int   g_count[BATCH];
__device__ volatile int g_flag[BATCH];

__global__ void init_kernel() {
    const int t = threadIdx.x;
    if (t < BATCH) { g_count[t] = 0; g_flag[t] = 0; }
}

// ---------------------------------------------------------------------------
// Fused kernel. grid = (CHUNKS, BATCH) = 3136 blocks, 256 threads.
// Phase A: load 32px x 256ch chunk into REGISTERS (8 float4/thread, __ldcg),
//          block partial sum -> g_partial; last-arriving block of each batch
//          (atomic counter) reduces 98 partials, runs squeeze->relu6->excite
//          ->hsigmoid, publishes gate + flag.
// Phase B: spin on flag[b] (thread 0, nanosleep), then multiply the register-
//          held x by the gate and streaming-store to out.
// x is read from DRAM exactly once; no SMEM chunk cache (1.3KB smem only).
// Batches resolve in dispatch order -> short spins, no deadlock.
// ---------------------------------------------------------------------------
__global__ __launch_bounds__(256) void fused_kernel(
    const float4* __restrict__ x4,
    const float*  __restrict__ w1,
    const float*  __restrict__ w2,
    float4*       __restrict__ out4)
{
    const int chunk = blockIdx.x;
    const int b     = blockIdx.y;
    const int tid   = threadIdx.x;
    const int c4    = tid & (C4 - 1);
    const int pr    = tid >> 6;

    const size_t base = ((size_t)(b * HW + chunk * PPC + pr)) * C4 + c4;

    // ---- Phase A: load x into registers, partial GAP -----------------------
    float4 v[8];
#pragma unroll
    for (int i = 0; i < 8; ++i) {
        v[i] = __ldcg(&x4[base + (size_t)i * 4 * C4]);
    }

    float4 acc = make_float4(0.f, 0.f, 0.f, 0.f);
#pragma unroll
    for (int i = 0; i < 8; ++i) {
        acc.x += v[i].x; acc.y += v[i].y; acc.z += v[i].z; acc.w += v[i].w;
    }

    __shared__ float red[4 * C];       // 4KB: 4 subgroups x 256 channels
    __shared__ int   s_last;
    red[pr * C + c4 * 4 + 0] = acc.x;  // avoid float4 smem bank pressure
    red[pr * C + c4 * 4 + 1] = acc.y;
    red[pr * C + c4 * 4 + 2] = acc.z;
    red[pr * C + c4 * 4 + 3] = acc.w;
    __syncthreads();

    // 256 threads: one channel each
    {
        float p0 = red[tid] + red[C + tid] + red[2 * C + tid] + red[3 * C + tid];
        __stcg(&g_partial[(b * CHUNKS + chunk) * C + tid], p0);
    }
    __threadfence();                   // publish partial before counter bump
    __syncthreads();

    if (tid == 0) {
        s_last = (atomicAdd(&g_count[b], 1) == CHUNKS - 1);
    }
    __syncthreads();

    // ---- FC on the last-arriving block of this batch ----------------------
    if (s_last) {
        __shared__ float s[C];
        __shared__ float h[CR];

        float sum = 0.0f;
#pragma unroll 7
        for (int k = 0; k < CHUNKS; ++k) {
            sum += __ldcg(&g_partial[(b * CHUNKS + k) * C + tid]);
        }
        s[tid] = sum * (1.0f / (float)HW);
        __syncthreads();

        if (tid < CR) {
            float a2 = 0.0f;
#pragma unroll 8
            for (int c = 0; c < C; ++c) {
                a2 += s[c] * w1[c * CR + tid];
            }
            h[tid] = fminf(fmaxf(a2, 0.0f), 6.0f);
        }
        __syncthreads();

        float a2 = 0.0f;
#pragma unroll
        for (int r = 0; r < CR; ++r) {
            a2 += h[r] * w2[r * C + tid];
        }
        float gate = fminf(fmaxf(a2 + 3.0f, 0.0f), 6.0f) * (1.0f / 6.0f);
        __stcg(&g_gate[b * C + tid], gate);
        __threadfence();               // publish gate before flag
        __syncthreads();
        if (tid == 0) g_flag[b] = 1;
    }

    // ---- Phase B: wait for gate, multiply register-held x, store ----------
    if (tid == 0) {
        while (g_flag[b] == 0) { __nanosleep(100); }
    }
    __syncthreads();
    __threadfence();                   // acquire: order gate read after flag

    const float4 gv = __ldcg(&((const float4*)g_gate)[b * C4 + c4]);

#pragma unroll
    for (int i = 0; i < 8; ++i) {
        v[i].x *= gv.x; v[i].y *= gv.y; v[i].z *= gv.z; v[i].w *= gv.w;
        __stcs(&out4[base + (size_t)i * 4 * C4], v[i]);
    }
}

extern "C" void kernel_launch(void* const* d_in, const int* in_sizes, int n_in,
                              void* d_out, int out_size) {
    const float* x  = (const float*)d_in[0];
    const float* w1 = (const float*)d_in[1];
    const float* w2 = (const float*)d_in[2];
    float* out      = (float*)d_out;

    init_kernel<<<1, 64>>>();
    dim3 grid(CHUNKS, BATCH);
    fused_kernel<<<grid, 256>>>((const float4*)x, w1, w2, (float4*)out);
}

// round 9
// speedup vs baseline: 2.1858x; 2.1858x over previous
#include <cuda_runtime.h>
#include <cstdint>

#define BATCH  32
#define HW     3136
#define C      256
#define CR     64
#define PPC    16            // pixels per chunk
#define CHUNKS 196           // HW / PPC
#define NG     32            // channel groups of 8 floats (C/8)

// Scratch (allocation-free per harness rules)
__device__ float g_partial[BATCH * CHUNKS * C];
__device__ float g_gate[BATCH * C];

// ---- 256-bit L2 eviction-priority primitives (sm_100+) ---------------------
__device__ __forceinline__ void ld256_evict_last(const float* p, uint32_t* u) {
    asm volatile("ld.global.nc.L2::evict_last.v8.b32 {%0,%1,%2,%3,%4,%5,%6,%7}, [%8];"
                 : "=r"(u[0]), "=r"(u[1]), "=r"(u[2]), "=r"(u[3]),
                   "=r"(u[4]), "=r"(u[5]), "=r"(u[6]), "=r"(u[7])
                 : "l"(p));
}
__device__ __forceinline__ void ld256_evict_first(const float* p, uint32_t* u) {
    asm volatile("ld.global.nc.L2::evict_first.v8.b32 {%0,%1,%2,%3,%4,%5,%6,%7}, [%8];"
                 : "=r"(u[0]), "=r"(u[1]), "=r"(u[2]), "=r"(u[3]),
                   "=r"(u[4]), "=r"(u[5]), "=r"(u[6]), "=r"(u[7])
                 : "l"(p));
}
__device__ __forceinline__ void st256_evict_first(float* p, const uint32_t* u) {
    asm volatile("st.global.L2::evict_first.v8.b32 [%0], {%1,%2,%3,%4,%5,%6,%7,%8};"
                 :: "l"(p),
                    "r"(u[0]), "r"(u[1]), "r"(u[2]), "r"(u[3]),
                    "r"(u[4]), "r"(u[5]), "r"(u[6]), "r"(u[7]));
}

// ---------------------------------------------------------------------------
// gap_kernel: grid = (CHUNKS, BATCH) = 6272 blocks, 256 threads.
// c8 = tid&31 (8-float channel group), pr = tid>>5 (8 pixel subgroups).
// Each thread: 2 x 256-bit loads with L2::evict_last (pins x in L2).
// SMEM reduce across the 8 pixel subgroups -> per-block partial.
// ---------------------------------------------------------------------------
__global__ __launch_bounds__(256) void gap_kernel(const float* __restrict__ x)
{
    const int chunk = blockIdx.x;
    const int b     = blockIdx.y;
    const int tid   = threadIdx.x;
    const int c8    = tid & (NG - 1);
    const int pr    = tid >> 5;

    const float* xp = x + ((size_t)(b * HW + chunk * PPC + pr)) * C + c8 * 8;

    uint32_t u0[8], u1[8];
    ld256_evict_last(xp,                  u0);
    ld256_evict_last(xp + (size_t)8 * C,  u1);

    __shared__ float red[8 * C];       // 8KB
    float* rp = &red[pr * C + c8 * 8];
#pragma unroll
    for (int k = 0; k < 8; ++k) {
        rp[k] = __uint_as_float(u0[k]) + __uint_as_float(u1[k]);
    }
    __syncthreads();

    // 256 threads: one channel each, sum 8 subgroups
    float p0 = 0.0f;
#pragma unroll
    for (int g = 0; g < 8; ++g) {
        p0 += red[g * C + tid];
    }
    g_partial[(b * CHUNKS + chunk) * C + tid] = p0;
}

// ---------------------------------------------------------------------------
// fc_kernel: 32 blocks x 256 threads. 4-way accumulate over 196 partials,
// then squeeze->relu6->excite->hsigmoid.
// ---------------------------------------------------------------------------
__global__ __launch_bounds__(256) void fc_kernel(const float* __restrict__ w1,
                                                 const float* __restrict__ w2)
{
    const int b = blockIdx.x;
    const int t = threadIdx.x;

    __shared__ float s[C];
    __shared__ float h[CR];

    float s0 = 0.f, s1 = 0.f, s2 = 0.f, s3 = 0.f;
#pragma unroll
    for (int k = 0; k < CHUNKS; k += 4) {
        s0 += __ldcg(&g_partial[(b * CHUNKS + k + 0) * C + t]);
        s1 += __ldcg(&g_partial[(b * CHUNKS + k + 1) * C + t]);
        s2 += __ldcg(&g_partial[(b * CHUNKS + k + 2) * C + t]);
        s3 += __ldcg(&g_partial[(b * CHUNKS + k + 3) * C + t]);
    }
    s[t] = ((s0 + s1) + (s2 + s3)) * (1.0f / (float)HW);
    __syncthreads();

    if (t < CR) {
        float acc = 0.0f;
#pragma unroll 8
        for (int c = 0; c < C; ++c) {
            acc += s[c] * w1[c * CR + t];
        }
        h[t] = fminf(fmaxf(acc, 0.0f), 6.0f);
    }
    __syncthreads();

    float acc = 0.0f;
#pragma unroll
    for (int r = 0; r < CR; ++r) {
        acc += h[r] * w2[r * C + t];
    }
    g_gate[b * C + t] = fminf(fmaxf(acc + 3.0f, 0.0f), 6.0f) * (1.0f / 6.0f);
}

// ---------------------------------------------------------------------------
// mul_kernel: grid = (CHUNKS, BATCH), 256 threads. x-reads expected L2 hits
// (pinned by gap's evict_last); reads use evict_first (x is dead after this),
// writes use evict_first so the out stream never evicts live x lines.
// ---------------------------------------------------------------------------
__global__ __launch_bounds__(256) void mul_kernel(const float* __restrict__ x,
                                                  float* __restrict__ out)
{
    const int chunk = blockIdx.x;
    const int b     = blockIdx.y;
    const int tid   = threadIdx.x;
    const int c8    = tid & (NG - 1);
    const int pr    = tid >> 5;

    // gate for channels [c8*8, c8*8+8)
    float g[8];
    {
        const float4 ga = __ldcg(&((const float4*)g_gate)[b * (C / 4) + c8 * 2]);
        const float4 gb = __ldcg(&((const float4*)g_gate)[b * (C / 4) + c8 * 2 + 1]);
        g[0] = ga.x; g[1] = ga.y; g[2] = ga.z; g[3] = ga.w;
        g[4] = gb.x; g[5] = gb.y; g[6] = gb.z; g[7] = gb.w;
    }

    const size_t off = ((size_t)(b * HW + chunk * PPC + pr)) * C + c8 * 8;
    const float* xp = x + off;
    float*       op = out + off;

    uint32_t u0[8], u1[8];
    ld256_evict_first(xp,                 u0);
    ld256_evict_first(xp + (size_t)8 * C, u1);

#pragma unroll
    for (int k = 0; k < 8; ++k) {
        u0[k] = __float_as_uint(__uint_as_float(u0[k]) * g[k]);
        u1[k] = __float_as_uint(__uint_as_float(u1[k]) * g[k]);
    }

    st256_evict_first(op,                 u0);
    st256_evict_first(op + (size_t)8 * C, u1);
}

extern "C" void kernel_launch(void* const* d_in, const int* in_sizes, int n_in,
                              void* d_out, int out_size) {
    const float* x  = (const float*)d_in[0];
    const float* w1 = (const float*)d_in[1];
    const float* w2 = (const float*)d_in[2];
    float* out      = (float*)d_out;

    dim3 grid(CHUNKS, BATCH);
    gap_kernel<<<grid, 256>>>(x);
    fc_kernel<<<BATCH, 256>>>(w1, w2);
    mul_kernel<<<grid, 256>>>(x, out);
}